// round 2
// baseline (speedup 1.0000x reference)
#include <cuda_runtime.h>
#include <cstdint>

#define BATCH 2
#define CCH 128
#define ICH 16
#define NP 9216              // 16*24*24
#define QT 64                // queries per CTA
#define TM 256               // keys per smem tile
#define NT (NP / TM)         // 36 tiles
#define NCTA_PER_B (NP / QT) // 144
#define LOG2E 1.4426950408889634f

// dynamic smem layout (floats):
//  [0      .. 16384)  k/v double-buffered tiles (2 bufs x (4096 k + 4096 v))
//                     ALIASED after mainloop by: partials [8][64][17] (8704) + inv[64] @8704
//  [16384  .. 18432)  Wo (128x16)
//  [18432  .. 18560)  bo
#define SMEM_FLOATS 18560
#define SMEM_BYTES (SMEM_FLOATS * 4)

typedef unsigned long long ull;

__device__ float g_q[BATCH * NP * ICH];
__device__ float g_k[BATCH * NP * ICH];
__device__ float g_v[BATCH * NP * ICH];

// ---- packed f32x2 helpers (FFMA2 path — 2 MACs per fma-pipe slot) ----
static __device__ __forceinline__ ull fmul2(ull a, ull b) {
    ull d; asm("mul.rn.f32x2 %0, %1, %2;" : "=l"(d) : "l"(a), "l"(b)); return d;
}
static __device__ __forceinline__ ull ffma2(ull a, ull b, ull c) {
    ull d; asm("fma.rn.f32x2 %0, %1, %2, %3;" : "=l"(d) : "l"(a), "l"(b), "l"(c)); return d;
}
static __device__ __forceinline__ ull fadd2(ull a, ull b) {
    ull d; asm("add.rn.f32x2 %0, %1, %2;" : "=l"(d) : "l"(a), "l"(b)); return d;
}
static __device__ __forceinline__ ull pk2(float x, float y) {
    ull d; asm("mov.b64 %0, {%1, %2};" : "=l"(d) : "f"(x), "f"(y)); return d;
}
static __device__ __forceinline__ float2 upk(ull a) {
    float2 v; asm("mov.b64 {%0, %1}, %2;" : "=f"(v.x), "=f"(v.y) : "l"(a)); return v;
}
static __device__ __forceinline__ float ex2f(float x) {
    float r; asm("ex2.approx.f32 %0, %1;" : "=f"(r) : "f"(x)); return r;
}
static __device__ __forceinline__ void cpasync16(void* smem_dst, const void* gmem_src) {
    unsigned sa = (unsigned)__cvta_generic_to_shared(smem_dst);
    asm volatile("cp.async.cg.shared.global [%0], [%1], 16;" :: "r"(sa), "l"(gmem_src));
}

// ============================================================================
// Kernel 1: q,k,v = W{q,k,v} @ x + b  -> scratch as [B, N, 16] rows.
// q additionally pre-scaled by log2(e) so logits feed ex2 directly.
// ============================================================================
__global__ void __launch_bounds__(256) qkv_kernel(
    const float* __restrict__ x,
    const float* __restrict__ Wq, const float* __restrict__ bq,
    const float* __restrict__ Wk, const float* __restrict__ bk,
    const float* __restrict__ Wv, const float* __restrict__ bv)
{
    __shared__ float sWq[ICH * CCH], sWk[ICH * CCH], sWv[ICH * CCH];
    __shared__ float sb[3 * ICH];
    for (int i = threadIdx.x; i < ICH * CCH; i += 256) {
        sWq[i] = Wq[i]; sWk[i] = Wk[i]; sWv[i] = Wv[i];
    }
    if (threadIdx.x < ICH)            sb[threadIdx.x] = bq[threadIdx.x];
    else if (threadIdx.x < 2 * ICH)   sb[threadIdx.x] = bk[threadIdx.x - ICH];
    else if (threadIdx.x < 3 * ICH)   sb[threadIdx.x] = bv[threadIdx.x - 2 * ICH];
    __syncthreads();

    int gid = blockIdx.x * 256 + threadIdx.x;   // 0 .. B*N-1
    int b = gid / NP, n = gid % NP;
    const float* xb = x + (size_t)b * CCH * NP + n;

    float aq[ICH], ak[ICH], av[ICH];
    #pragma unroll
    for (int i = 0; i < ICH; i++) { aq[i] = 0.f; ak[i] = 0.f; av[i] = 0.f; }

    for (int c = 0; c < CCH; c += 4) {
        float x0 = xb[(size_t)(c + 0) * NP];
        float x1 = xb[(size_t)(c + 1) * NP];
        float x2 = xb[(size_t)(c + 2) * NP];
        float x3 = xb[(size_t)(c + 3) * NP];
        #pragma unroll
        for (int i = 0; i < ICH; i++) {
            float4 wq = *(const float4*)&sWq[i * CCH + c];
            aq[i] = fmaf(wq.x, x0, fmaf(wq.y, x1, fmaf(wq.z, x2, fmaf(wq.w, x3, aq[i]))));
            float4 wk = *(const float4*)&sWk[i * CCH + c];
            ak[i] = fmaf(wk.x, x0, fmaf(wk.y, x1, fmaf(wk.z, x2, fmaf(wk.w, x3, ak[i]))));
            float4 wv = *(const float4*)&sWv[i * CCH + c];
            av[i] = fmaf(wv.x, x0, fmaf(wv.y, x1, fmaf(wv.z, x2, fmaf(wv.w, x3, av[i]))));
        }
    }
    float* qo = g_q + (size_t)gid * ICH;
    float* ko = g_k + (size_t)gid * ICH;
    float* vo = g_v + (size_t)gid * ICH;
    #pragma unroll
    for (int i = 0; i < ICH; i++) {
        qo[i] = (aq[i] + sb[i]) * LOG2E;
        ko[i] = ak[i] + sb[ICH + i];
        vo[i] = av[i] + sb[2 * ICH + i];
    }
}

// ============================================================================
// Kernel 2: fused attention (no-max softmax) + Wo projection + residual.
// CTA = 256 thr / 8 warps, 64 queries (2 per lane). Each warp owns a 32-key
// slice of every 256-key tile; partials reduced through smem at the end.
// ============================================================================
__global__ void __launch_bounds__(256, 2) attn_kernel(
    const float* __restrict__ x, const float* __restrict__ Wo,
    const float* __restrict__ bo, const float* __restrict__ gamma,
    float* __restrict__ y)
{
    extern __shared__ float sm[];
    float* sWo = sm + 2 * 8192;          // 2048 floats
    float* sbo = sWo + ICH * CCH;        // 128 floats
    float* inv = sm + 8 * QT * 17;       // 64 floats @ 8704 (alias region)

    const int tid = threadIdx.x;
    const int w = tid >> 5, l = tid & 31;
    const int b  = blockIdx.x / NCTA_PER_B;
    const int n0 = (blockIdx.x % NCTA_PER_B) * QT;

    for (int i = tid; i < ICH * CCH; i += 256) sWo[i] = Wo[i];
    if (tid < CCH) sbo[tid] = bo[tid];

    // Each lane holds queries n0+l (A) and n0+l+32 (B): q rows as 8 f32x2 each
    ull qA[8], qB[8];
    {
        const ulonglong2* qa2 = (const ulonglong2*)(g_q + (size_t)(b * NP + n0 + l) * ICH);
        const ulonglong2* qb2 = (const ulonglong2*)(g_q + (size_t)(b * NP + n0 + l + 32) * ICH);
        #pragma unroll
        for (int r = 0; r < 4; r++) {
            ulonglong2 ta = qa2[r]; qA[2 * r] = ta.x; qA[2 * r + 1] = ta.y;
            ulonglong2 tb = qb2[r]; qB[2 * r] = tb.x; qB[2 * r + 1] = tb.y;
        }
    }

    ull dA[8], dB[8];
    #pragma unroll
    for (int r = 0; r < 8; r++) { dA[r] = 0ull; dB[r] = 0ull; }
    ull den = 0ull;   // {denomA, denomB}

    const float* kgb = g_k + (size_t)b * NP * ICH;
    const float* vgb = g_v + (size_t)b * NP * ICH;

    // prologue: tile 0 -> buf 0
    {
        const float4* kg = (const float4*)kgb;
        const float4* vg = (const float4*)vgb;
        float4* kb4 = (float4*)(sm);
        float4* vb4 = (float4*)(sm + 4096);
        #pragma unroll
        for (int r = 0; r < 4; r++) {
            int i = r * 256 + tid;
            cpasync16(kb4 + i, kg + i);
            cpasync16(vb4 + i, vg + i);
        }
        asm volatile("cp.async.commit_group;" ::: "memory");
    }

    int buf = 0;
    for (int t = 0; t < NT; t++) {
        if (t + 1 < NT) {
            const float4* kg = (const float4*)(kgb + (size_t)(t + 1) * TM * ICH);
            const float4* vg = (const float4*)(vgb + (size_t)(t + 1) * TM * ICH);
            float4* kb4 = (float4*)(sm + (buf ^ 1) * 8192);
            float4* vb4 = (float4*)(sm + (buf ^ 1) * 8192 + 4096);
            #pragma unroll
            for (int r = 0; r < 4; r++) {
                int i = r * 256 + tid;
                cpasync16(kb4 + i, kg + i);
                cpasync16(vb4 + i, vg + i);
            }
            asm volatile("cp.async.commit_group;" ::: "memory");
            asm volatile("cp.async.wait_group 1;" ::: "memory");
        } else {
            asm volatile("cp.async.wait_group 0;" ::: "memory");
        }
        __syncthreads();

        const float* kb = sm + buf * 8192 + (w * 32) * ICH;
        const float* vb = sm + buf * 8192 + 4096 + (w * 32) * ICH;
        #pragma unroll 4
        for (int j = 0; j < 32; j++) {
            const ulonglong2* kr = (const ulonglong2*)(kb + j * ICH);
            ulonglong2 p0 = kr[0], p1 = kr[1];
            ull a0 = fmul2(qA[0], p0.x); ull a1 = fmul2(qA[1], p0.y);
            ull b0 = fmul2(qB[0], p0.x); ull b1 = fmul2(qB[1], p0.y);
            a0 = ffma2(qA[2], p1.x, a0); a1 = ffma2(qA[3], p1.y, a1);
            b0 = ffma2(qB[2], p1.x, b0); b1 = ffma2(qB[3], p1.y, b1);
            ulonglong2 p2 = kr[2], p3 = kr[3];
            a0 = ffma2(qA[4], p2.x, a0); a1 = ffma2(qA[5], p2.y, a1);
            b0 = ffma2(qB[4], p2.x, b0); b1 = ffma2(qB[5], p2.y, b1);
            a0 = ffma2(qA[6], p3.x, a0); a1 = ffma2(qA[7], p3.y, a1);
            b0 = ffma2(qB[6], p3.x, b0); b1 = ffma2(qB[7], p3.y, b1);
            a0 = fadd2(a0, a1); b0 = fadd2(b0, b1);
            float2 fa = upk(a0), fb = upk(b0);
            float pA = ex2f(fa.x + fa.y);     // logits already in log2 domain
            float pB = ex2f(fb.x + fb.y);
            den = fadd2(den, pk2(pA, pB));
            ull pA2 = pk2(pA, pA), pB2 = pk2(pB, pB);
            const ulonglong2* vr = (const ulonglong2*)(vb + j * ICH);
            ulonglong2 v0 = vr[0], v1 = vr[1], v2 = vr[2], v3 = vr[3];
            dA[0] = ffma2(pA2, v0.x, dA[0]); dA[1] = ffma2(pA2, v0.y, dA[1]);
            dA[2] = ffma2(pA2, v1.x, dA[2]); dA[3] = ffma2(pA2, v1.y, dA[3]);
            dA[4] = ffma2(pA2, v2.x, dA[4]); dA[5] = ffma2(pA2, v2.y, dA[5]);
            dA[6] = ffma2(pA2, v3.x, dA[6]); dA[7] = ffma2(pA2, v3.y, dA[7]);
            dB[0] = ffma2(pB2, v0.x, dB[0]); dB[1] = ffma2(pB2, v0.y, dB[1]);
            dB[2] = ffma2(pB2, v1.x, dB[2]); dB[3] = ffma2(pB2, v1.y, dB[3]);
            dB[4] = ffma2(pB2, v2.x, dB[4]); dB[5] = ffma2(pB2, v2.y, dB[5]);
            dB[6] = ffma2(pB2, v3.x, dB[6]); dB[7] = ffma2(pB2, v3.y, dB[7]);
        }
        __syncthreads();
        buf ^= 1;
    }

    // write per-warp partials (aliases exhausted tile buffers)
    {
        float* pr = sm + (w * QT + l) * 17;
        #pragma unroll
        for (int r = 0; r < 8; r++) { float2 f = upk(dA[r]); pr[2 * r] = f.x; pr[2 * r + 1] = f.y; }
        float2 dn = upk(den);
        pr[16] = dn.x;
        float* pr2 = sm + (w * QT + l + 32) * 17;
        #pragma unroll
        for (int r = 0; r < 8; r++) { float2 f = upk(dB[r]); pr2[2 * r] = f.x; pr2[2 * r + 1] = f.y; }
        pr2[16] = dn.y;
    }
    __syncthreads();

    // reduce across the 8 warp-slices into the w=0 block
    for (int idx = tid; idx < QT * 17; idx += 256) {
        float s = sm[idx];
        #pragma unroll
        for (int ww = 1; ww < 8; ww++) s += sm[ww * QT * 17 + idx];
        sm[idx] = s;
    }
    __syncthreads();
    if (tid < QT) inv[tid] = 1.0f / sm[tid * 17 + 16];
    __syncthreads();

    // epilogue: y[b,c,n] = gamma * (Wo @ (acc/den) + bo) + x  (coalesced over n)
    const float gam = gamma[0];
    for (int idx = tid; idx < CCH * QT; idx += 256) {
        int c = idx >> 6;
        int nl = idx & 63;
        const float* wr = sWo + c * ICH;
        const float* ov = sm + nl * 17;
        float acc = 0.f;
        #pragma unroll
        for (int i = 0; i < ICH; i++) acc = fmaf(wr[i], ov[i], acc);
        float outv = acc * inv[nl] + sbo[c];
        size_t gi = ((size_t)(b * CCH + c)) * NP + (n0 + nl);
        y[gi] = gam * outv + x[gi];
    }
}

extern "C" void kernel_launch(void* const* d_in, const int* in_sizes, int n_in,
                              void* d_out, int out_size) {
    const float* x     = (const float*)d_in[0];
    const float* Wq    = (const float*)d_in[1];
    const float* bq    = (const float*)d_in[2];
    const float* Wk    = (const float*)d_in[3];
    const float* bk    = (const float*)d_in[4];
    const float* Wv    = (const float*)d_in[5];
    const float* bv    = (const float*)d_in[6];
    const float* Wo    = (const float*)d_in[7];
    const float* bo    = (const float*)d_in[8];
    const float* gamma = (const float*)d_in[9];
    float* y = (float*)d_out;

    cudaFuncSetAttribute(attn_kernel, cudaFuncAttributeMaxDynamicSharedMemorySize, SMEM_BYTES);

    qkv_kernel<<<(BATCH * NP) / 256, 256>>>(x, Wq, bq, Wk, bk, Wv, bv);
    attn_kernel<<<BATCH * NCTA_PER_B, 256, SMEM_BYTES>>>(x, Wo, bo, gamma, y);
}

// round 3
// speedup vs baseline: 1.0072x; 1.0072x over previous
#include <cuda_runtime.h>
#include <cstdint>

#define BATCH 2
#define CCH 128
#define ICH 16
#define NP 9216              // 16*24*24
#define QT 64                // queries per CTA
#define TM 256               // keys per smem tile
#define NT (NP / TM)         // 36 tiles
#define NCTA_PER_B (NP / QT) // 144
#define LOG2E 1.4426950408889634f

// dynamic smem layout (floats):
//  [0      .. 16384)  k/v double-buffered tiles (2 bufs x (4096 k + 4096 v))
//                     ALIASED after mainloop by: partials [8][64][17] (8704) + inv[64] @8704
//  [16384  .. 18432)  Wo (128x16)
//  [18432  .. 18560)  bo
#define SMEM_FLOATS 18560
#define SMEM_BYTES (SMEM_FLOATS * 4)

typedef unsigned long long ull;

__device__ float g_q[BATCH * NP * ICH];
__device__ float g_k[BATCH * NP * ICH];
__device__ float g_v[BATCH * NP * ICH];

// ---- packed f32x2 helpers (FFMA2 path — 2 MACs per fma-pipe slot) ----
static __device__ __forceinline__ ull fmul2(ull a, ull b) {
    ull d; asm("mul.rn.f32x2 %0, %1, %2;" : "=l"(d) : "l"(a), "l"(b)); return d;
}
static __device__ __forceinline__ ull ffma2(ull a, ull b, ull c) {
    ull d; asm("fma.rn.f32x2 %0, %1, %2, %3;" : "=l"(d) : "l"(a), "l"(b), "l"(c)); return d;
}
static __device__ __forceinline__ ull fadd2(ull a, ull b) {
    ull d; asm("add.rn.f32x2 %0, %1, %2;" : "=l"(d) : "l"(a), "l"(b)); return d;
}
static __device__ __forceinline__ ull pk2(float x, float y) {
    ull d; asm("mov.b64 %0, {%1, %2};" : "=l"(d) : "f"(x), "f"(y)); return d;
}
static __device__ __forceinline__ float2 upk(ull a) {
    float2 v; asm("mov.b64 {%0, %1}, %2;" : "=f"(v.x), "=f"(v.y) : "l"(a)); return v;
}
static __device__ __forceinline__ float ex2f(float x) {
    float r; asm("ex2.approx.f32 %0, %1;" : "=f"(r) : "f"(x)); return r;
}
static __device__ __forceinline__ void cpasync16(void* smem_dst, const void* gmem_src) {
    unsigned sa = (unsigned)__cvta_generic_to_shared(smem_dst);
    asm volatile("cp.async.cg.shared.global [%0], [%1], 16;" :: "r"(sa), "l"(gmem_src));
}

// ============================================================================
// Kernel 1: q,k,v = W{q,k,v} @ x + b  -> scratch as [B, N, 16] rows.
// q additionally pre-scaled by log2(e) so logits feed ex2 directly.
// ============================================================================
__global__ void __launch_bounds__(256) qkv_kernel(
    const float* __restrict__ x,
    const float* __restrict__ Wq, const float* __restrict__ bq,
    const float* __restrict__ Wk, const float* __restrict__ bk,
    const float* __restrict__ Wv, const float* __restrict__ bv)
{
    __shared__ float sWq[ICH * CCH], sWk[ICH * CCH], sWv[ICH * CCH];
    __shared__ float sb[3 * ICH];
    for (int i = threadIdx.x; i < ICH * CCH; i += 256) {
        sWq[i] = Wq[i]; sWk[i] = Wk[i]; sWv[i] = Wv[i];
    }
    if (threadIdx.x < ICH)            sb[threadIdx.x] = bq[threadIdx.x];
    else if (threadIdx.x < 2 * ICH)   sb[threadIdx.x] = bk[threadIdx.x - ICH];
    else if (threadIdx.x < 3 * ICH)   sb[threadIdx.x] = bv[threadIdx.x - 2 * ICH];
    __syncthreads();

    int gid = blockIdx.x * 256 + threadIdx.x;   // 0 .. B*N-1
    int b = gid / NP, n = gid % NP;
    const float* xb = x + (size_t)b * CCH * NP + n;

    float aq[ICH], ak[ICH], av[ICH];
    #pragma unroll
    for (int i = 0; i < ICH; i++) { aq[i] = 0.f; ak[i] = 0.f; av[i] = 0.f; }

    for (int c = 0; c < CCH; c += 4) {
        float x0 = xb[(size_t)(c + 0) * NP];
        float x1 = xb[(size_t)(c + 1) * NP];
        float x2 = xb[(size_t)(c + 2) * NP];
        float x3 = xb[(size_t)(c + 3) * NP];
        #pragma unroll
        for (int i = 0; i < ICH; i++) {
            float4 wq = *(const float4*)&sWq[i * CCH + c];
            aq[i] = fmaf(wq.x, x0, fmaf(wq.y, x1, fmaf(wq.z, x2, fmaf(wq.w, x3, aq[i]))));
            float4 wk = *(const float4*)&sWk[i * CCH + c];
            ak[i] = fmaf(wk.x, x0, fmaf(wk.y, x1, fmaf(wk.z, x2, fmaf(wk.w, x3, ak[i]))));
            float4 wv = *(const float4*)&sWv[i * CCH + c];
            av[i] = fmaf(wv.x, x0, fmaf(wv.y, x1, fmaf(wv.z, x2, fmaf(wv.w, x3, av[i]))));
        }
    }
    float* qo = g_q + (size_t)gid * ICH;
    float* ko = g_k + (size_t)gid * ICH;
    float* vo = g_v + (size_t)gid * ICH;
    #pragma unroll
    for (int i = 0; i < ICH; i++) {
        qo[i] = (aq[i] + sb[i]) * LOG2E;
        ko[i] = ak[i] + sb[ICH + i];
        vo[i] = av[i] + sb[2 * ICH + i];
    }
}

// ============================================================================
// Kernel 2: fused attention (no-max softmax) + Wo projection + residual.
// CTA = 256 thr / 8 warps, 64 queries (2 per lane). Each warp owns a 32-key
// slice of every 256-key tile; partials reduced through smem at the end.
// ============================================================================
__global__ void __launch_bounds__(256, 2) attn_kernel(
    const float* __restrict__ x, const float* __restrict__ Wo,
    const float* __restrict__ bo, const float* __restrict__ gamma,
    float* __restrict__ y)
{
    extern __shared__ float sm[];
    float* sWo = sm + 2 * 8192;          // 2048 floats
    float* sbo = sWo + ICH * CCH;        // 128 floats
    float* inv = sm + 8 * QT * 17;       // 64 floats @ 8704 (alias region)

    const int tid = threadIdx.x;
    const int w = tid >> 5, l = tid & 31;
    const int b  = blockIdx.x / NCTA_PER_B;
    const int n0 = (blockIdx.x % NCTA_PER_B) * QT;

    for (int i = tid; i < ICH * CCH; i += 256) sWo[i] = Wo[i];
    if (tid < CCH) sbo[tid] = bo[tid];

    // Each lane holds queries n0+l (A) and n0+l+32 (B): q rows as 8 f32x2 each
    ull qA[8], qB[8];
    {
        const ulonglong2* qa2 = (const ulonglong2*)(g_q + (size_t)(b * NP + n0 + l) * ICH);
        const ulonglong2* qb2 = (const ulonglong2*)(g_q + (size_t)(b * NP + n0 + l + 32) * ICH);
        #pragma unroll
        for (int r = 0; r < 4; r++) {
            ulonglong2 ta = qa2[r]; qA[2 * r] = ta.x; qA[2 * r + 1] = ta.y;
            ulonglong2 tb = qb2[r]; qB[2 * r] = tb.x; qB[2 * r + 1] = tb.y;
        }
    }

    ull dA[8], dB[8];
    #pragma unroll
    for (int r = 0; r < 8; r++) { dA[r] = 0ull; dB[r] = 0ull; }
    ull den = 0ull;   // {denomA, denomB}

    const float* kgb = g_k + (size_t)b * NP * ICH;
    const float* vgb = g_v + (size_t)b * NP * ICH;

    // prologue: tile 0 -> buf 0
    {
        const float4* kg = (const float4*)kgb;
        const float4* vg = (const float4*)vgb;
        float4* kb4 = (float4*)(sm);
        float4* vb4 = (float4*)(sm + 4096);
        #pragma unroll
        for (int r = 0; r < 4; r++) {
            int i = r * 256 + tid;
            cpasync16(kb4 + i, kg + i);
            cpasync16(vb4 + i, vg + i);
        }
        asm volatile("cp.async.commit_group;" ::: "memory");
    }

    int buf = 0;
    for (int t = 0; t < NT; t++) {
        if (t + 1 < NT) {
            const float4* kg = (const float4*)(kgb + (size_t)(t + 1) * TM * ICH);
            const float4* vg = (const float4*)(vgb + (size_t)(t + 1) * TM * ICH);
            float4* kb4 = (float4*)(sm + (buf ^ 1) * 8192);
            float4* vb4 = (float4*)(sm + (buf ^ 1) * 8192 + 4096);
            #pragma unroll
            for (int r = 0; r < 4; r++) {
                int i = r * 256 + tid;
                cpasync16(kb4 + i, kg + i);
                cpasync16(vb4 + i, vg + i);
            }
            asm volatile("cp.async.commit_group;" ::: "memory");
            asm volatile("cp.async.wait_group 1;" ::: "memory");
        } else {
            asm volatile("cp.async.wait_group 0;" ::: "memory");
        }
        __syncthreads();

        const float* kb = sm + buf * 8192 + (w * 32) * ICH;
        const float* vb = sm + buf * 8192 + 4096 + (w * 32) * ICH;
        #pragma unroll 4
        for (int j = 0; j < 32; j++) {
            const ulonglong2* kr = (const ulonglong2*)(kb + j * ICH);
            ulonglong2 p0 = kr[0], p1 = kr[1];
            ull a0 = fmul2(qA[0], p0.x); ull a1 = fmul2(qA[1], p0.y);
            ull b0 = fmul2(qB[0], p0.x); ull b1 = fmul2(qB[1], p0.y);
            a0 = ffma2(qA[2], p1.x, a0); a1 = ffma2(qA[3], p1.y, a1);
            b0 = ffma2(qB[2], p1.x, b0); b1 = ffma2(qB[3], p1.y, b1);
            ulonglong2 p2 = kr[2], p3 = kr[3];
            a0 = ffma2(qA[4], p2.x, a0); a1 = ffma2(qA[5], p2.y, a1);
            b0 = ffma2(qB[4], p2.x, b0); b1 = ffma2(qB[5], p2.y, b1);
            a0 = ffma2(qA[6], p3.x, a0); a1 = ffma2(qA[7], p3.y, a1);
            b0 = ffma2(qB[6], p3.x, b0); b1 = ffma2(qB[7], p3.y, b1);
            a0 = fadd2(a0, a1); b0 = fadd2(b0, b1);
            float2 fa = upk(a0), fb = upk(b0);
            float pA = ex2f(fa.x + fa.y);     // logits already in log2 domain
            float pB = ex2f(fb.x + fb.y);
            den = fadd2(den, pk2(pA, pB));
            ull pA2 = pk2(pA, pA), pB2 = pk2(pB, pB);
            const ulonglong2* vr = (const ulonglong2*)(vb + j * ICH);
            ulonglong2 v0 = vr[0], v1 = vr[1], v2 = vr[2], v3 = vr[3];
            dA[0] = ffma2(pA2, v0.x, dA[0]); dA[1] = ffma2(pA2, v0.y, dA[1]);
            dA[2] = ffma2(pA2, v1.x, dA[2]); dA[3] = ffma2(pA2, v1.y, dA[3]);
            dA[4] = ffma2(pA2, v2.x, dA[4]); dA[5] = ffma2(pA2, v2.y, dA[5]);
            dA[6] = ffma2(pA2, v3.x, dA[6]); dA[7] = ffma2(pA2, v3.y, dA[7]);
            dB[0] = ffma2(pB2, v0.x, dB[0]); dB[1] = ffma2(pB2, v0.y, dB[1]);
            dB[2] = ffma2(pB2, v1.x, dB[2]); dB[3] = ffma2(pB2, v1.y, dB[3]);
            dB[4] = ffma2(pB2, v2.x, dB[4]); dB[5] = ffma2(pB2, v2.y, dB[5]);
            dB[6] = ffma2(pB2, v3.x, dB[6]); dB[7] = ffma2(pB2, v3.y, dB[7]);
        }
        __syncthreads();
        buf ^= 1;
    }

    // write per-warp partials (aliases exhausted tile buffers)
    {
        float* pr = sm + (w * QT + l) * 17;
        #pragma unroll
        for (int r = 0; r < 8; r++) { float2 f = upk(dA[r]); pr[2 * r] = f.x; pr[2 * r + 1] = f.y; }
        float2 dn = upk(den);
        pr[16] = dn.x;
        float* pr2 = sm + (w * QT + l + 32) * 17;
        #pragma unroll
        for (int r = 0; r < 8; r++) { float2 f = upk(dB[r]); pr2[2 * r] = f.x; pr2[2 * r + 1] = f.y; }
        pr2[16] = dn.y;
    }
    __syncthreads();

    // reduce across the 8 warp-slices into the w=0 block
    for (int idx = tid; idx < QT * 17; idx += 256) {
        float s = sm[idx];
        #pragma unroll
        for (int ww = 1; ww < 8; ww++) s += sm[ww * QT * 17 + idx];
        sm[idx] = s;
    }
    __syncthreads();
    if (tid < QT) inv[tid] = 1.0f / sm[tid * 17 + 16];
    __syncthreads();

    // epilogue: y[b,c,n] = gamma * (Wo @ (acc/den) + bo) + x  (coalesced over n)
    const float gam = gamma[0];
    for (int idx = tid; idx < CCH * QT; idx += 256) {
        int c = idx >> 6;
        int nl = idx & 63;
        const float* wr = sWo + c * ICH;
        const float* ov = sm + nl * 17;
        float acc = 0.f;
        #pragma unroll
        for (int i = 0; i < ICH; i++) acc = fmaf(wr[i], ov[i], acc);
        float outv = acc * inv[nl] + sbo[c];
        size_t gi = ((size_t)(b * CCH + c)) * NP + (n0 + nl);
        y[gi] = gam * outv + x[gi];
    }
}

extern "C" void kernel_launch(void* const* d_in, const int* in_sizes, int n_in,
                              void* d_out, int out_size) {
    const float* x     = (const float*)d_in[0];
    const float* Wq    = (const float*)d_in[1];
    const float* bq    = (const float*)d_in[2];
    const float* Wk    = (const float*)d_in[3];
    const float* bk    = (const float*)d_in[4];
    const float* Wv    = (const float*)d_in[5];
    const float* bv    = (const float*)d_in[6];
    const float* Wo    = (const float*)d_in[7];
    const float* bo    = (const float*)d_in[8];
    const float* gamma = (const float*)d_in[9];
    float* y = (float*)d_out;

    cudaFuncSetAttribute(attn_kernel, cudaFuncAttributeMaxDynamicSharedMemorySize, SMEM_BYTES);

    qkv_kernel<<<(BATCH * NP) / 256, 256>>>(x, Wq, bq, Wk, bk, Wv, bv);
    attn_kernel<<<BATCH * NCTA_PER_B, 256, SMEM_BYTES>>>(x, Wo, bo, gamma, y);
}

// round 5
// speedup vs baseline: 1.9466x; 1.9328x over previous
#include <cuda_runtime.h>
#include <cuda_fp16.h>
#include <cstdint>

#define BATCH 2
#define CCH 128
#define ICH 16
#define NP 9216
#define QB 64                // queries per CTA
#define KT 128               // keys per tile
#define NT (NP / KT)         // 72
#define NQB (NP / QB)        // 144
#define LOG2E 1.4426950408889634f

// smem byte offsets (K stride 80B/key: hi ch0-15 @0, lo @32, pad; V stride 272B/row)
#define K0_OFF 0
#define K1_OFF 10240
#define V0_OFF 20480
#define V1_OFF 29184
#define WO_OFF 37888
#define BO_OFF 46080
#define SO_OFF 46592
#define SMEM_BYTES 50944

typedef unsigned int u32;

__device__ __align__(16) u32 g_q2[BATCH * NP * 16];            // per query: 8 u32 fp16-hi pairs, 8 lo
__device__ __align__(16) u32 g_k2[BATCH * NP * 16];            // same for K
__device__ __align__(16) unsigned short g_vt[BATCH * 32 * NP]; // rows 0-15 Vh (bf16), 16-31 Vl

static __device__ __forceinline__ float ex2f(float x) {
    float r; asm("ex2.approx.f32 %0, %1;" : "=f"(r) : "f"(x)); return r;
}
static __device__ __forceinline__ u32 pack_bf16(float a, float b) {   // truncation hi
    return __byte_perm(__float_as_uint(a), __float_as_uint(b), 0x7632);
}
static __device__ __forceinline__ float lo_of(float a) {
    return a - __uint_as_float(__float_as_uint(a) & 0xFFFF0000u);
}
static __device__ __forceinline__ u32 pack_f16(__half a, __half b) {
    return (u32)__half_as_ushort(a) | ((u32)__half_as_ushort(b) << 16);
}
static __device__ __forceinline__ void cpasync16(void* s, const void* g) {
    u32 a = (u32)__cvta_generic_to_shared(s);
    asm volatile("cp.async.cg.shared.global [%0], [%1], 16;" :: "r"(a), "l"(g));
}
#define CP_COMMIT() asm volatile("cp.async.commit_group;" ::: "memory")

#define MMA_F16(d, a, b0, b1) \
    asm volatile("mma.sync.aligned.m16n8k16.row.col.f32.f16.f16.f32 " \
        "{%0,%1,%2,%3},{%4,%5,%6,%7},{%8,%9},{%0,%1,%2,%3};" \
        : "+f"((d)[0]), "+f"((d)[1]), "+f"((d)[2]), "+f"((d)[3]) \
        : "r"((a)[0]), "r"((a)[1]), "r"((a)[2]), "r"((a)[3]), "r"(b0), "r"(b1))

#define MMA_BF16(d, a, b0, b1) \
    asm volatile("mma.sync.aligned.m16n8k16.row.col.f32.bf16.bf16.f32 " \
        "{%0,%1,%2,%3},{%4,%5,%6,%7},{%8,%9},{%0,%1,%2,%3};" \
        : "+f"((d)[0]), "+f"((d)[1]), "+f"((d)[2]), "+f"((d)[3]) \
        : "r"((a)[0]), "r"((a)[1]), "r"((a)[2]), "r"((a)[3]), "r"(b0), "r"(b1))

// ============================================================================
// Kernel 1: qkv projections -> fp16 hi/lo Q,K ; bf16 hi/lo V (transposed)
// ============================================================================
__global__ void __launch_bounds__(256) qkv_kernel(
    const float* __restrict__ x,
    const float* __restrict__ Wq, const float* __restrict__ bq,
    const float* __restrict__ Wk, const float* __restrict__ bk,
    const float* __restrict__ Wv, const float* __restrict__ bv)
{
    __shared__ float sWq[ICH * CCH], sWk[ICH * CCH], sWv[ICH * CCH];
    __shared__ float sb[3 * ICH];
    for (int i = threadIdx.x; i < ICH * CCH; i += 256) {
        sWq[i] = Wq[i]; sWk[i] = Wk[i]; sWv[i] = Wv[i];
    }
    if (threadIdx.x < ICH)            sb[threadIdx.x] = bq[threadIdx.x];
    else if (threadIdx.x < 2 * ICH)   sb[threadIdx.x] = bk[threadIdx.x - ICH];
    else if (threadIdx.x < 3 * ICH)   sb[threadIdx.x] = bv[threadIdx.x - 2 * ICH];
    __syncthreads();

    int gid = blockIdx.x * 256 + threadIdx.x;
    int b = gid / NP, n = gid % NP;
    const float* xb = x + (size_t)b * CCH * NP + n;

    float aq[ICH], ak[ICH], av[ICH];
    #pragma unroll
    for (int i = 0; i < ICH; i++) { aq[i] = 0.f; ak[i] = 0.f; av[i] = 0.f; }

    for (int c = 0; c < CCH; c += 4) {
        float x0 = xb[(size_t)(c + 0) * NP];
        float x1 = xb[(size_t)(c + 1) * NP];
        float x2 = xb[(size_t)(c + 2) * NP];
        float x3 = xb[(size_t)(c + 3) * NP];
        #pragma unroll
        for (int i = 0; i < ICH; i++) {
            float4 wq = *(const float4*)&sWq[i * CCH + c];
            aq[i] = fmaf(wq.x, x0, fmaf(wq.y, x1, fmaf(wq.z, x2, fmaf(wq.w, x3, aq[i]))));
            float4 wk = *(const float4*)&sWk[i * CCH + c];
            ak[i] = fmaf(wk.x, x0, fmaf(wk.y, x1, fmaf(wk.z, x2, fmaf(wk.w, x3, ak[i]))));
            float4 wv = *(const float4*)&sWv[i * CCH + c];
            av[i] = fmaf(wv.x, x0, fmaf(wv.y, x1, fmaf(wv.z, x2, fmaf(wv.w, x3, av[i]))));
        }
    }

    float qf[ICH], kf[ICH];
    #pragma unroll
    for (int i = 0; i < ICH; i++) {
        qf[i] = (aq[i] + sb[i]) * LOG2E;
        kf[i] = ak[i] + sb[ICH + i];
    }
    u32* qo = g_q2 + (size_t)gid * 16;
    u32* ko = g_k2 + (size_t)gid * 16;
    #pragma unroll
    for (int j = 0; j < 8; j++) {
        __half qh0 = __float2half_rn(qf[2 * j]),     qh1 = __float2half_rn(qf[2 * j + 1]);
        float  qlo0 = qf[2 * j] - __half2float(qh0), qlo1 = qf[2 * j + 1] - __half2float(qh1);
        qo[j]     = pack_f16(qh0, qh1);
        qo[8 + j] = pack_f16(__float2half_rn(qlo0), __float2half_rn(qlo1));
        __half kh0 = __float2half_rn(kf[2 * j]),     kh1 = __float2half_rn(kf[2 * j + 1]);
        float  klo0 = kf[2 * j] - __half2float(kh0), klo1 = kf[2 * j + 1] - __half2float(kh1);
        ko[j]     = pack_f16(kh0, kh1);
        ko[8 + j] = pack_f16(__float2half_rn(klo0), __float2half_rn(klo1));
    }
    unsigned short* vt = g_vt + (size_t)b * 32 * NP + n;
    #pragma unroll
    for (int i = 0; i < ICH; i++) {
        float vv = av[i] + sb[2 * ICH + i];
        vt[(size_t)i * NP]        = (unsigned short)(__float_as_uint(vv) >> 16);
        vt[(size_t)(16 + i) * NP] = (unsigned short)(__float_as_uint(lo_of(vv)) >> 16);
    }
}

// ---------------- tile loaders (128 threads) ----------------
static __device__ __forceinline__ void load_k_tile(const char* gk, char* dst, int t, int tid) {
    const char* src = gk + (size_t)t * KT * 64;
    #pragma unroll
    for (int r = 0; r < 4; r++) {
        int idx = r * 128 + tid;
        int key = idx >> 2, c = idx & 3;
        cpasync16(dst + key * 80 + c * 16, src + key * 64 + c * 16);
    }
}
static __device__ __forceinline__ void load_v_tile(const char* gv, char* dst, int t, int tid) {
    #pragma unroll
    for (int r = 0; r < 4; r++) {
        int idx = r * 128 + tid;
        int row = idx >> 4, c = idx & 15;
        cpasync16(dst + row * 272 + c * 16, gv + (size_t)row * (NP * 2) + t * 256 + c * 16);
    }
}

// ============================================================================
// Kernel 2: HMMA flash attention + Wo projection + residual
// ============================================================================
__global__ void __launch_bounds__(128, 2) attn_kernel(
    const float* __restrict__ x, const float* __restrict__ Wo,
    const float* __restrict__ bo, const float* __restrict__ gamma,
    float* __restrict__ y)
{
    extern __shared__ char smc[];
    const int tid = threadIdx.x;
    const int w = tid >> 5, lane = tid & 31;
    const int gr = lane >> 2, tg = lane & 3;
    const int b  = blockIdx.x / NQB;
    const int q0 = (blockIdx.x % NQB) * QB;

    float* sWo = (float*)(smc + WO_OFF);
    float* sbo = (float*)(smc + BO_OFF);
    float* sO  = (float*)(smc + SO_OFF);
    for (int i = tid; i < ICH * CCH; i += 128) sWo[i] = Wo[i];
    if (tid < CCH) sbo[tid] = bo[tid];

    // Q fragments for this warp's 16 queries (rows w*16 + gr, +8)
    const u32* qp  = g_q2 + (size_t)(b * NP + q0 + w * 16 + gr) * 16;
    const u32* qp8 = qp + 8 * 16;
    u32 qh[4], ql[4];
    qh[0] = qp[tg];     qh[1] = qp8[tg];     qh[2] = qp[tg + 4];  qh[3] = qp8[tg + 4];
    ql[0] = qp[8 + tg]; ql[1] = qp8[8 + tg]; ql[2] = qp[12 + tg]; ql[3] = qp8[12 + tg];

    float oA[2][4] = {}, oB[2][4] = {}, oC[2][4] = {};
    float dn0 = 0.f, dn1 = 0.f;

    const char* gk = (const char*)(g_k2 + (size_t)b * NP * 16);
    const char* gv = (const char*)(g_vt + (size_t)b * 32 * NP);

    load_k_tile(gk, smc + K0_OFF, 0, tid);
    load_v_tile(gv, smc + V0_OFF, 0, tid);
    CP_COMMIT();

    int buf = 0;
    for (int t = 0; t < NT; t++) {
        if (t + 1 < NT) {
            load_k_tile(gk, smc + (buf ? K0_OFF : K1_OFF), t + 1, tid);
            load_v_tile(gv, smc + (buf ? V0_OFF : V1_OFF), t + 1, tid);
            CP_COMMIT();
            asm volatile("cp.async.wait_group 1;" ::: "memory");
        } else {
            asm volatile("cp.async.wait_group 0;" ::: "memory");
        }
        __syncthreads();

        const char* kb = smc + (buf ? K1_OFF : K0_OFF);
        const char* vb = smc + (buf ? V1_OFF : V0_OFF);

        #pragma unroll
        for (int ck = 0; ck < 8; ck++) {
            float s0[4] = {0.f, 0.f, 0.f, 0.f};
            float s1[4] = {0.f, 0.f, 0.f, 0.f};
            const char* ka = kb + (ck * 16 + gr) * 80 + tg * 4;
            {
                u32 b0 = *(const u32*)ka,        b1 = *(const u32*)(ka + 16);
                u32 c0 = *(const u32*)(ka + 32), c1 = *(const u32*)(ka + 48);
                MMA_F16(s0, qh, b0, b1);
                MMA_F16(s0, ql, b0, b1);
                MMA_F16(s0, qh, c0, c1);
            }
            {
                const char* ka1 = ka + 8 * 80;
                u32 b0 = *(const u32*)ka1,        b1 = *(const u32*)(ka1 + 16);
                u32 c0 = *(const u32*)(ka1 + 32), c1 = *(const u32*)(ka1 + 48);
                MMA_F16(s1, qh, b0, b1);
                MMA_F16(s1, ql, b0, b1);
                MMA_F16(s1, qh, c0, c1);
            }
            float p00 = ex2f(s0[0]), p01 = ex2f(s0[1]), p02 = ex2f(s0[2]), p03 = ex2f(s0[3]);
            float p10 = ex2f(s1[0]), p11 = ex2f(s1[1]), p12 = ex2f(s1[2]), p13 = ex2f(s1[3]);
            dn0 += p00 + p01 + p10 + p11;
            dn1 += p02 + p03 + p12 + p13;
            u32 pah[4], pal[4];
            pah[0] = pack_bf16(p00, p01); pah[1] = pack_bf16(p02, p03);
            pah[2] = pack_bf16(p10, p11); pah[3] = pack_bf16(p12, p13);
            pal[0] = pack_bf16(lo_of(p00), lo_of(p01)); pal[1] = pack_bf16(lo_of(p02), lo_of(p03));
            pal[2] = pack_bf16(lo_of(p10), lo_of(p11)); pal[3] = pack_bf16(lo_of(p12), lo_of(p13));

            #pragma unroll
            for (int cb = 0; cb < 2; cb++) {
                const char* va = vb + (cb * 8 + gr) * 272 + ck * 32 + tg * 4;
                u32 vh0 = *(const u32*)va,               vh1 = *(const u32*)(va + 16);
                u32 vl0 = *(const u32*)(va + 16 * 272),  vl1 = *(const u32*)(va + 16 * 272 + 16);
                MMA_BF16(oA[cb], pah, vh0, vh1);
                MMA_BF16(oB[cb], pal, vh0, vh1);
                MMA_BF16(oC[cb], pah, vl0, vl1);
            }
        }
        __syncthreads();
        buf ^= 1;
    }

    // denominator quad-reduce (lanes gr*4+0..3 hold disjoint column subsets)
    dn0 += __shfl_xor_sync(0xFFFFFFFFu, dn0, 1);
    dn0 += __shfl_xor_sync(0xFFFFFFFFu, dn0, 2);
    dn1 += __shfl_xor_sync(0xFFFFFFFFu, dn1, 1);
    dn1 += __shfl_xor_sync(0xFFFFFFFFu, dn1, 2);
    float id0 = 1.0f / dn0, id1 = 1.0f / dn1;

    #pragma unroll
    for (int cb = 0; cb < 2; cb++) {
        int col = cb * 8 + tg * 2;
        int r0 = w * 16 + gr, r1 = r0 + 8;
        sO[r0 * 17 + col]     = (oA[cb][0] + oB[cb][0] + oC[cb][0]) * id0;
        sO[r0 * 17 + col + 1] = (oA[cb][1] + oB[cb][1] + oC[cb][1]) * id0;
        sO[r1 * 17 + col]     = (oA[cb][2] + oB[cb][2] + oC[cb][2]) * id1;
        sO[r1 * 17 + col + 1] = (oA[cb][3] + oB[cb][3] + oC[cb][3]) * id1;
    }
    __syncthreads();

    const float gam = gamma[0];
    for (int idx = tid; idx < CCH * QB; idx += 128) {
        int c = idx >> 6, q = idx & 63;
        const float* wr = sWo + c * ICH;
        const float* ov = sO + q * 17;
        float acc = 0.f;
        #pragma unroll
        for (int i = 0; i < ICH; i++) acc = fmaf(wr[i], ov[i], acc);
        size_t gi = ((size_t)(b * CCH + c)) * NP + (q0 + q);
        y[gi] = gam * (acc + sbo[c]) + x[gi];
    }
}

extern "C" void kernel_launch(void* const* d_in, const int* in_sizes, int n_in,
                              void* d_out, int out_size) {
    const float* x     = (const float*)d_in[0];
    const float* Wq    = (const float*)d_in[1];
    const float* bq    = (const float*)d_in[2];
    const float* Wk    = (const float*)d_in[3];
    const float* bk    = (const float*)d_in[4];
    const float* Wv    = (const float*)d_in[5];
    const float* bv    = (const float*)d_in[6];
    const float* Wo    = (const float*)d_in[7];
    const float* bo    = (const float*)d_in[8];
    const float* gamma = (const float*)d_in[9];
    float* y = (float*)d_out;

    cudaFuncSetAttribute(attn_kernel, cudaFuncAttributeMaxDynamicSharedMemorySize, SMEM_BYTES);

    qkv_kernel<<<(BATCH * NP) / 256, 256>>>(x, Wq, bq, Wk, bk, Wv, bv);
    attn_kernel<<<BATCH * NQB, 128, SMEM_BYTES>>>(x, Wo, bo, gamma, y);
}

// round 6
// speedup vs baseline: 2.0419x; 1.0489x over previous
#include <cuda_runtime.h>
#include <cuda_fp16.h>
#include <cstdint>

#define BATCH 2
#define CCH 128
#define ICH 16
#define NP 9216
#define QB 64                // queries per CTA
#define KT 128               // keys per tile
#define NT (NP / KT)         // 72
#define NQB (NP / QB)        // 144
#define LOG2E 1.4426950408889634f

// smem byte offsets (K stride 80B/key; V stride 272B/row)
#define K0_OFF 0
#define K1_OFF 10240
#define V0_OFF 20480
#define V1_OFF 29184
#define WO_OFF 37888
#define BO_OFF 46080
#define SO_OFF 46592
#define SMEM_BYTES 50944
// cross-warp partial area aliases K0 tile buffer after the mainloop
// layout: [64 queries][18]: cols 0-15 output partial, col 16 = dn partial

typedef unsigned int u32;

__device__ __align__(16) u32 g_q2[BATCH * NP * 16];            // per query: 8 u32 fp16-hi pairs, 8 lo
__device__ __align__(16) u32 g_k2[BATCH * NP * 16];            // same for K
__device__ __align__(16) unsigned short g_vt[BATCH * 32 * NP]; // rows 0-15 Vh (bf16), 16-31 Vl

static __device__ __forceinline__ float ex2f(float x) {
    float r; asm("ex2.approx.f32 %0, %1;" : "=f"(r) : "f"(x)); return r;
}
static __device__ __forceinline__ u32 pack_bf16(float a, float b) {
    return __byte_perm(__float_as_uint(a), __float_as_uint(b), 0x7632);
}
static __device__ __forceinline__ float lo_of(float a) {
    return a - __uint_as_float(__float_as_uint(a) & 0xFFFF0000u);
}
static __device__ __forceinline__ u32 pack_f16(__half a, __half b) {
    return (u32)__half_as_ushort(a) | ((u32)__half_as_ushort(b) << 16);
}
static __device__ __forceinline__ void cpasync16(void* s, const void* g) {
    u32 a = (u32)__cvta_generic_to_shared(s);
    asm volatile("cp.async.cg.shared.global [%0], [%1], 16;" :: "r"(a), "l"(g));
}
#define CP_COMMIT() asm volatile("cp.async.commit_group;" ::: "memory")

#define MMA_F16(d, a, b0, b1) \
    asm volatile("mma.sync.aligned.m16n8k16.row.col.f32.f16.f16.f32 " \
        "{%0,%1,%2,%3},{%4,%5,%6,%7},{%8,%9},{%0,%1,%2,%3};" \
        : "+f"((d)[0]), "+f"((d)[1]), "+f"((d)[2]), "+f"((d)[3]) \
        : "r"((a)[0]), "r"((a)[1]), "r"((a)[2]), "r"((a)[3]), "r"(b0), "r"(b1))

#define MMA_BF16(d, a, b0, b1) \
    asm volatile("mma.sync.aligned.m16n8k16.row.col.f32.bf16.bf16.f32 " \
        "{%0,%1,%2,%3},{%4,%5,%6,%7},{%8,%9},{%0,%1,%2,%3};" \
        : "+f"((d)[0]), "+f"((d)[1]), "+f"((d)[2]), "+f"((d)[3]) \
        : "r"((a)[0]), "r"((a)[1]), "r"((a)[2]), "r"((a)[3]), "r"(b0), "r"(b1))

// ============================================================================
// Kernel 1: qkv projections -> fp16 hi/lo Q,K ; bf16 hi/lo V (transposed)
// ============================================================================
__global__ void __launch_bounds__(256) qkv_kernel(
    const float* __restrict__ x,
    const float* __restrict__ Wq, const float* __restrict__ bq,
    const float* __restrict__ Wk, const float* __restrict__ bk,
    const float* __restrict__ Wv, const float* __restrict__ bv)
{
    __shared__ float sWq[ICH * CCH], sWk[ICH * CCH], sWv[ICH * CCH];
    __shared__ float sb[3 * ICH];
    for (int i = threadIdx.x; i < ICH * CCH; i += 256) {
        sWq[i] = Wq[i]; sWk[i] = Wk[i]; sWv[i] = Wv[i];
    }
    if (threadIdx.x < ICH)            sb[threadIdx.x] = bq[threadIdx.x];
    else if (threadIdx.x < 2 * ICH)   sb[threadIdx.x] = bk[threadIdx.x - ICH];
    else if (threadIdx.x < 3 * ICH)   sb[threadIdx.x] = bv[threadIdx.x - 2 * ICH];
    __syncthreads();

    int gid = blockIdx.x * 256 + threadIdx.x;
    int b = gid / NP, n = gid % NP;
    const float* xb = x + (size_t)b * CCH * NP + n;

    float aq[ICH], ak[ICH], av[ICH];
    #pragma unroll
    for (int i = 0; i < ICH; i++) { aq[i] = 0.f; ak[i] = 0.f; av[i] = 0.f; }

    for (int c = 0; c < CCH; c += 4) {
        float x0 = xb[(size_t)(c + 0) * NP];
        float x1 = xb[(size_t)(c + 1) * NP];
        float x2 = xb[(size_t)(c + 2) * NP];
        float x3 = xb[(size_t)(c + 3) * NP];
        #pragma unroll
        for (int i = 0; i < ICH; i++) {
            float4 wq = *(const float4*)&sWq[i * CCH + c];
            aq[i] = fmaf(wq.x, x0, fmaf(wq.y, x1, fmaf(wq.z, x2, fmaf(wq.w, x3, aq[i]))));
            float4 wk = *(const float4*)&sWk[i * CCH + c];
            ak[i] = fmaf(wk.x, x0, fmaf(wk.y, x1, fmaf(wk.z, x2, fmaf(wk.w, x3, ak[i]))));
            float4 wv = *(const float4*)&sWv[i * CCH + c];
            av[i] = fmaf(wv.x, x0, fmaf(wv.y, x1, fmaf(wv.z, x2, fmaf(wv.w, x3, av[i]))));
        }
    }

    float qf[ICH], kf[ICH];
    #pragma unroll
    for (int i = 0; i < ICH; i++) {
        qf[i] = (aq[i] + sb[i]) * LOG2E;
        kf[i] = ak[i] + sb[ICH + i];
    }
    u32* qo = g_q2 + (size_t)gid * 16;
    u32* ko = g_k2 + (size_t)gid * 16;
    #pragma unroll
    for (int j = 0; j < 8; j++) {
        __half qh0 = __float2half_rn(qf[2 * j]),     qh1 = __float2half_rn(qf[2 * j + 1]);
        float  qlo0 = qf[2 * j] - __half2float(qh0), qlo1 = qf[2 * j + 1] - __half2float(qh1);
        qo[j]     = pack_f16(qh0, qh1);
        qo[8 + j] = pack_f16(__float2half_rn(qlo0), __float2half_rn(qlo1));
        __half kh0 = __float2half_rn(kf[2 * j]),     kh1 = __float2half_rn(kf[2 * j + 1]);
        float  klo0 = kf[2 * j] - __half2float(kh0), klo1 = kf[2 * j + 1] - __half2float(kh1);
        ko[j]     = pack_f16(kh0, kh1);
        ko[8 + j] = pack_f16(__float2half_rn(klo0), __float2half_rn(klo1));
    }
    unsigned short* vt = g_vt + (size_t)b * 32 * NP + n;
    #pragma unroll
    for (int i = 0; i < ICH; i++) {
        float vv = av[i] + sb[2 * ICH + i];
        vt[(size_t)i * NP]        = (unsigned short)(__float_as_uint(vv) >> 16);
        vt[(size_t)(16 + i) * NP] = (unsigned short)(__float_as_uint(lo_of(vv)) >> 16);
    }
}

// ---------------- tile loaders (256 threads) ----------------
static __device__ __forceinline__ void load_k_tile(const char* gk, char* dst, int t, int tid) {
    const char* src = gk + (size_t)t * KT * 64;
    #pragma unroll
    for (int r = 0; r < 2; r++) {
        int idx = r * 256 + tid;
        int key = idx >> 2, c = idx & 3;
        cpasync16(dst + key * 80 + c * 16, src + key * 64 + c * 16);
    }
}
static __device__ __forceinline__ void load_v_tile(const char* gv, char* dst, int t, int tid) {
    #pragma unroll
    for (int r = 0; r < 2; r++) {
        int idx = r * 256 + tid;
        int row = idx >> 4, c = idx & 15;
        cpasync16(dst + row * 272 + c * 16, gv + (size_t)row * (NP * 2) + t * 256 + c * 16);
    }
}

// ============================================================================
// Kernel 2: HMMA flash attention, key-split across warp halves
// ============================================================================
__global__ void __launch_bounds__(256, 2) attn_kernel(
    const float* __restrict__ x, const float* __restrict__ Wo,
    const float* __restrict__ bo, const float* __restrict__ gamma,
    float* __restrict__ y)
{
    extern __shared__ char smc[];
    const int tid = threadIdx.x;
    const int w = tid >> 5, lane = tid & 31;
    const int wq = w & 3;            // query group (16 queries)
    const int wk = w >> 2;           // key half of each tile
    const int gr = lane >> 2, tg = lane & 3;
    const int b  = blockIdx.x / NQB;
    const int q0 = (blockIdx.x % NQB) * QB;

    float* sWo = (float*)(smc + WO_OFF);
    float* sbo = (float*)(smc + BO_OFF);
    float* sO  = (float*)(smc + SO_OFF);
    for (int i = tid; i < ICH * CCH; i += 256) sWo[i] = Wo[i];
    if (tid < CCH) sbo[tid] = bo[tid];

    // Q fragments for this warp's 16 queries (rows wq*16 + gr, +8)
    const u32* qp  = g_q2 + (size_t)(b * NP + q0 + wq * 16 + gr) * 16;
    const u32* qp8 = qp + 8 * 16;
    u32 qh[4], ql[4];
    qh[0] = qp[tg];     qh[1] = qp8[tg];     qh[2] = qp[tg + 4];  qh[3] = qp8[tg + 4];
    ql[0] = qp[8 + tg]; ql[1] = qp8[8 + tg]; ql[2] = qp[12 + tg]; ql[3] = qp8[12 + tg];

    float oA[2][4] = {}, oB[2][4] = {};
    float dn0 = 0.f, dn1 = 0.f;

    const char* gk = (const char*)(g_k2 + (size_t)b * NP * 16);
    const char* gv = (const char*)(g_vt + (size_t)b * 32 * NP);

    load_k_tile(gk, smc + K0_OFF, 0, tid);
    load_v_tile(gv, smc + V0_OFF, 0, tid);
    CP_COMMIT();

    int buf = 0;
    for (int t = 0; t < NT; t++) {
        if (t + 1 < NT) {
            load_k_tile(gk, smc + (buf ? K0_OFF : K1_OFF), t + 1, tid);
            load_v_tile(gv, smc + (buf ? V0_OFF : V1_OFF), t + 1, tid);
            CP_COMMIT();
            asm volatile("cp.async.wait_group 1;" ::: "memory");
        } else {
            asm volatile("cp.async.wait_group 0;" ::: "memory");
        }
        __syncthreads();

        const char* kb = smc + (buf ? K1_OFF : K0_OFF);
        const char* vb = smc + (buf ? V1_OFF : V0_OFF);

        #pragma unroll
        for (int c2 = 0; c2 < 4; c2++) {
            const int ck = wk * 4 + c2;   // this warp's key chunk (16 keys)
            float s0[4] = {0.f, 0.f, 0.f, 0.f};
            float s1[4] = {0.f, 0.f, 0.f, 0.f};
            const char* ka = kb + (ck * 16 + gr) * 80 + tg * 4;
            {
                u32 b0 = *(const u32*)ka,        b1 = *(const u32*)(ka + 16);
                u32 c0 = *(const u32*)(ka + 32), c1 = *(const u32*)(ka + 48);
                MMA_F16(s0, qh, b0, b1);
                MMA_F16(s0, ql, b0, b1);
                MMA_F16(s0, qh, c0, c1);
            }
            {
                const char* ka1 = ka + 8 * 80;
                u32 b0 = *(const u32*)ka1,        b1 = *(const u32*)(ka1 + 16);
                u32 c0 = *(const u32*)(ka1 + 32), c1 = *(const u32*)(ka1 + 48);
                MMA_F16(s1, qh, b0, b1);
                MMA_F16(s1, ql, b0, b1);
                MMA_F16(s1, qh, c0, c1);
            }
            float p00 = ex2f(s0[0]), p01 = ex2f(s0[1]), p02 = ex2f(s0[2]), p03 = ex2f(s0[3]);
            float p10 = ex2f(s1[0]), p11 = ex2f(s1[1]), p12 = ex2f(s1[2]), p13 = ex2f(s1[3]);
            dn0 += p00 + p01 + p10 + p11;
            dn1 += p02 + p03 + p12 + p13;
            u32 pah[4], pal[4];
            pah[0] = pack_bf16(p00, p01); pah[1] = pack_bf16(p02, p03);
            pah[2] = pack_bf16(p10, p11); pah[3] = pack_bf16(p12, p13);
            pal[0] = pack_bf16(lo_of(p00), lo_of(p01)); pal[1] = pack_bf16(lo_of(p02), lo_of(p03));
            pal[2] = pack_bf16(lo_of(p10), lo_of(p11)); pal[3] = pack_bf16(lo_of(p12), lo_of(p13));

            #pragma unroll
            for (int cb = 0; cb < 2; cb++) {
                const char* va = vb + (cb * 8 + gr) * 272 + ck * 32 + tg * 4;
                u32 vh0 = *(const u32*)va, vh1 = *(const u32*)(va + 16);
                MMA_BF16(oA[cb], pah, vh0, vh1);
                MMA_BF16(oB[cb], pal, vh0, vh1);
            }
        }
        __syncthreads();
        buf ^= 1;
    }

    // quad-reduce denominators (lanes tg=0..3 hold disjoint key-column subsets)
    dn0 += __shfl_xor_sync(0xFFFFFFFFu, dn0, 1);
    dn0 += __shfl_xor_sync(0xFFFFFFFFu, dn0, 2);
    dn1 += __shfl_xor_sync(0xFFFFFFFFu, dn1, 1);
    dn1 += __shfl_xor_sync(0xFFFFFFFFu, dn1, 2);

    // cross-warp-half reduction via smem (aliases dead K0 tile buffer)
    float* part = (float*)(smc + K0_OFF);   // [64][18]: 16 out cols + dn
    const int r0 = wq * 16 + gr, r1 = r0 + 8;
    if (wk == 1) {
        #pragma unroll
        for (int cb = 0; cb < 2; cb++) {
            int col = cb * 8 + tg * 2;
            part[r0 * 18 + col]     = oA[cb][0] + oB[cb][0];
            part[r0 * 18 + col + 1] = oA[cb][1] + oB[cb][1];
            part[r1 * 18 + col]     = oA[cb][2] + oB[cb][2];
            part[r1 * 18 + col + 1] = oA[cb][3] + oB[cb][3];
        }
        if (tg == 0) { part[r0 * 18 + 16] = dn0; part[r1 * 18 + 16] = dn1; }
    }
    __syncthreads();
    if (wk == 0) {
        float id0 = 1.0f / (dn0 + part[r0 * 18 + 16]);
        float id1 = 1.0f / (dn1 + part[r1 * 18 + 16]);
        #pragma unroll
        for (int cb = 0; cb < 2; cb++) {
            int col = cb * 8 + tg * 2;
            sO[r0 * 17 + col]     = (oA[cb][0] + oB[cb][0] + part[r0 * 18 + col])     * id0;
            sO[r0 * 17 + col + 1] = (oA[cb][1] + oB[cb][1] + part[r0 * 18 + col + 1]) * id0;
            sO[r1 * 17 + col]     = (oA[cb][2] + oB[cb][2] + part[r1 * 18 + col])     * id1;
            sO[r1 * 17 + col + 1] = (oA[cb][3] + oB[cb][3] + part[r1 * 18 + col + 1]) * id1;
        }
    }
    __syncthreads();

    // epilogue: y = gamma * (Wo @ O + bo) + x
    const float gam = gamma[0];
    for (int idx = tid; idx < CCH * QB; idx += 256) {
        int c = idx >> 6, q = idx & 63;
        const float* wr = sWo + c * ICH;
        const float* ov = sO + q * 17;
        float acc = 0.f;
        #pragma unroll
        for (int i = 0; i < ICH; i++) acc = fmaf(wr[i], ov[i], acc);
        size_t gi = ((size_t)(b * CCH + c)) * NP + (q0 + q);
        y[gi] = gam * (acc + sbo[c]) + x[gi];
    }
}

extern "C" void kernel_launch(void* const* d_in, const int* in_sizes, int n_in,
                              void* d_out, int out_size) {
    const float* x     = (const float*)d_in[0];
    const float* Wq    = (const float*)d_in[1];
    const float* bq    = (const float*)d_in[2];
    const float* Wk    = (const float*)d_in[3];
    const float* bk    = (const float*)d_in[4];
    const float* Wv    = (const float*)d_in[5];
    const float* bv    = (const float*)d_in[6];
    const float* Wo    = (const float*)d_in[7];
    const float* bo    = (const float*)d_in[8];
    const float* gamma = (const float*)d_in[9];
    float* y = (float*)d_out;

    cudaFuncSetAttribute(attn_kernel, cudaFuncAttributeMaxDynamicSharedMemorySize, SMEM_BYTES);

    qkv_kernel<<<(BATCH * NP) / 256, 256>>>(x, Wq, bq, Wk, bk, Wv, bv);
    attn_kernel<<<BATCH * NQB, 256, SMEM_BYTES>>>(x, Wo, bo, gamma, y);
}